// round 4
// baseline (speedup 1.0000x reference)
#include <cuda_runtime.h>
#include <cstdint>
#include <math.h>

// ---------------------------------------------------------------------------
// Problem constants
// ---------------------------------------------------------------------------
static constexpr int kB = 8;
static constexpr int kS = 2048;
static constexpr int kD = 256;
static constexpr int kM = kB * kS;
static constexpr int QCH = 64;       // softmax/colsum: 32 rows per chunk
static constexpr int N_KCHUNK = 32;  // output split over keys

// Scratch (static device memory)
__device__ float g_Nh[kM * kD];
__device__ float g_Nl[kM * kD];
__device__ float g_Wqh[kD * kD];
__device__ float g_Wql[kD * kD];
__device__ float g_Wkh[kD * kD];
__device__ float g_Wkl[kD * kD];
__device__ float g_Wvh[kD * kD];
__device__ float g_Wvl[kD * kD];
__device__ float g_Qh[kB * kS * kD];
__device__ float g_Ql[kB * kS * kD];
__device__ float g_Kh[kB * kS * kD];
__device__ float g_Kl[kB * kS * kD];
__device__ float g_V[kB * kS * kD];
__device__ float g_P[(size_t)kB * kS * kS];
__device__ float g_w[kB * kS];
__device__ float g_wpart[QCH * kB * kS];
__device__ float g_opart[N_KCHUNK * kB * kD];

#if defined(__CUDA_ARCH__) && defined(__CUDA_ARCH_FEAT_SM103_ALL)
#define HAS_TCGEN05 1
#else
#define HAS_TCGEN05 0
#endif

// ---------------------------------------------------------------------------
// Shared memory layout for pipe_gemm (tcgen05 path)
//   [0,8)    full[0]   [8,16)  full[1]
//   [16,24)  empty[0]  [24,32) empty[1]
//   [32,40)  done      [40,44) tmem ptr
//   [64,1088)   mask[256] ints
//   [1088,2112) bias[256] floats
//   [4096, 4096+2*96K) 2 stages: {Ah 16K, Al 16K, Bh 32K, Bl 32K}
// ---------------------------------------------------------------------------
static constexpr int CTRL_MASK = 64;
static constexpr int CTRL_BIAS = 1088;
static constexpr int TILES_OFF = 4096;
static constexpr int STAGE_BYTES = 98304;                 // 96 KB
static constexpr int SMEM_TOTAL = TILES_OFF + 2 * STAGE_BYTES;  // 200704

#define SMEM_SWIZZLE_128B(byte_offset) \
    ((byte_offset) ^ (((byte_offset) >> 3) & 0x70))

__device__ __forceinline__ uint32_t smem_to_u32_gen(const void* p) {
    uint32_t a;
    asm("{ .reg .u64 t; cvta.to.shared.u64 t, %1; cvt.u32.u64 %0, t; }"
        : "=r"(a) : "l"(p));
    return a;
}

__device__ __forceinline__ float to_tf32(float x) {
    float y;
    asm("cvt.rna.tf32.f32 %0, %1;" : "=f"(y) : "f"(x));
    return y;
}

#if HAS_TCGEN05
__device__ __forceinline__ uint32_t elect_one_pred() {
    uint32_t pred;
    asm volatile(
        "{\n\t.reg .pred p;\n\t"
        "elect.sync _|p, 0xFFFFFFFF;\n\t"
        "selp.b32 %0, 1, 0, p;\n\t}"
        : "=r"(pred));
    return pred;
}

#define TCGEN05_ALLOC(smem_result_addr, nCols) \
    asm volatile("tcgen05.alloc.cta_group::1.sync.aligned.shared::cta.b32 [%0], %1;" \
                 :: "r"((uint32_t)(smem_result_addr)), "r"((uint32_t)(nCols)) : "memory")
#define TCGEN05_DEALLOC(tmem_addr, nCols) \
    asm volatile("tcgen05.dealloc.cta_group::1.sync.aligned.b32 %0, %1;" \
                 :: "r"(tmem_addr), "r"((uint32_t)(nCols)))
#define TCGEN05_RELINQUISH() \
    asm volatile("tcgen05.relinquish_alloc_permit.cta_group::1.sync.aligned;")
#define TCGEN05_COMMIT(mbar_smem_addr) \
    asm volatile("tcgen05.commit.cta_group::1.mbarrier::arrive::one.shared::cluster.b64 [%0];" \
                 :: "r"((uint32_t)(mbar_smem_addr)) : "memory")
#define TCGEN05_FENCE_AFTER() \
    asm volatile("tcgen05.fence::after_thread_sync;" ::: "memory")
#define TCGEN05_WAIT_LD() \
    asm volatile("tcgen05.wait::ld.sync.aligned;" ::: "memory")
#define MBARRIER_INIT(mbar_smem_addr, count) \
    asm volatile("mbarrier.init.shared.b64 [%0], %1;" \
                 :: "r"((uint32_t)(mbar_smem_addr)), "r"((uint32_t)(count)) : "memory")
#define FENCE_PROXY_ASYNC_SHARED_CTA() \
    asm volatile("fence.proxy.async.shared::cta;" ::: "memory")

#define MBARRIER_WAIT_PARITY(mbar_smem_addr, phase_parity) do { \
    uint32_t _mbar = (uint32_t)(mbar_smem_addr); \
    uint32_t _parity = (uint32_t)(phase_parity); \
    uint32_t _done; \
    asm volatile( \
        "{\n\t.reg .pred p;\n\t" \
        "mbarrier.try_wait.parity.acquire.cta.shared::cta.b64 p, [%1], %2;\n\t" \
        "selp.b32 %0, 1, 0, p;\n\t}" \
        : "=r"(_done) : "r"(_mbar), "r"(_parity) : "memory"); \
    if (!_done) { \
        asm volatile( \
            "{\n\t.reg .pred P1;\n\t" \
            "WAIT_LOOP_%=:\n\t" \
            "mbarrier.try_wait.parity.acquire.cta.shared::cta.b64 P1, [%0], %1, 0x989680;\n\t" \
            "@P1 bra.uni WAIT_DONE_%=;\n\t" \
            "bra.uni WAIT_LOOP_%=;\n\t" \
            "WAIT_DONE_%=:\n\t}" \
            :: "r"(_mbar), "r"(_parity) : "memory"); \
    } \
} while(0)

#define TCGEN05_LD_32X32B_X32(r, tmem_addr) \
    asm volatile( \
        "tcgen05.ld.sync.aligned.32x32b.x32.b32 " \
        "{%0, %1, %2, %3, %4, %5, %6, %7, " \
        " %8, %9, %10, %11, %12, %13, %14, %15, " \
        " %16, %17, %18, %19, %20, %21, %22, %23, " \
        " %24, %25, %26, %27, %28, %29, %30, %31}, [%32];" \
        : "=r"((r)[0]),  "=r"((r)[1]),  "=r"((r)[2]),  "=r"((r)[3]), \
          "=r"((r)[4]),  "=r"((r)[5]),  "=r"((r)[6]),  "=r"((r)[7]), \
          "=r"((r)[8]),  "=r"((r)[9]),  "=r"((r)[10]), "=r"((r)[11]), \
          "=r"((r)[12]), "=r"((r)[13]), "=r"((r)[14]), "=r"((r)[15]), \
          "=r"((r)[16]), "=r"((r)[17]), "=r"((r)[18]), "=r"((r)[19]), \
          "=r"((r)[20]), "=r"((r)[21]), "=r"((r)[22]), "=r"((r)[23]), \
          "=r"((r)[24]), "=r"((r)[25]), "=r"((r)[26]), "=r"((r)[27]), \
          "=r"((r)[28]), "=r"((r)[29]), "=r"((r)[30]), "=r"((r)[31]) \
        : "r"(tmem_addr))

#define TCGEN05_MMA_TF32_SS(d_tmem, a_desc, b_desc, idesc, enable_d) do { \
    uint32_t _en = (enable_d) ? 1u : 0u; \
    uint32_t _zero = 0u; \
    asm volatile( \
        "{\n\t.reg .pred p;\n\t" \
        "setp.ne.u32 p, %5, 0;\n\t" \
        "tcgen05.mma.cta_group::1.kind::tf32 [%0], %1, %2, %3, {%4, %4, %4, %4}, p;\n\t" \
        "}" \
        :: "r"(d_tmem), "l"(a_desc), "l"(b_desc), "r"(idesc), "r"(_zero), "r"(_en) \
        : "memory"); \
} while(0)

static constexpr uint64_t SMEM_DESC_BASE_SW128 =
    (uint64_t(2)  << 61) | (uint64_t(1) << 46) | (uint64_t(64) << 32) | (uint64_t(1) << 16);
#define MAKE_SMEM_DESC(base_addr) \
    (SMEM_DESC_BASE_SW128 | ((uint64_t)((base_addr) >> 4) & 0x3FFF))

__device__ __forceinline__ void cp_async16(uint32_t dst, const void* src) {
    asm volatile("cp.async.cg.shared.global [%0], [%1], 16;" :: "r"(dst), "l"(src));
}
#define CPASYNC_MBAR_ARRIVE_NOINC(mbar) \
    asm volatile("cp.async.mbarrier.arrive.noinc.shared::cta.b64 [%0];" \
                 :: "r"((uint32_t)(mbar)) : "memory")
#endif  // HAS_TCGEN05

// ---------------------------------------------------------------------------
// Elementwise split:  h = tf32(x), l = tf32(x - h)
// ---------------------------------------------------------------------------
__global__ __launch_bounds__(256)
void split_kernel(const float* __restrict__ src,
                  float* __restrict__ dh, float* __restrict__ dl)
{
    const int i = blockIdx.x * 256 + threadIdx.x;
    float x = src[i];
    float h = to_tf32(x);
    dh[i] = h;
    dl[i] = to_tf32(x - h);
}

// ---------------------------------------------------------------------------
// Pipelined split-tf32 tcgen05 GEMM.
//   C[m,n] = sum_k A[m,k]*B[n,k]   (A = Ah+Al, B = Bh+Bl), BM=128, BN=256
// mode 0: C0 = tf32_hi(acc+bias), C1 = tf32_lo   (Q/K projections)
// mode 1: C0 = acc + bias                         (V projection)
// mode 2: C0 = acc*scale, masked cols -> -inf     (scores)
// ---------------------------------------------------------------------------
__global__ __launch_bounds__(256)
void pipe_gemm(const float* __restrict__ Ah, const float* __restrict__ Al,
               const float* __restrict__ Bh, const float* __restrict__ Bl,
               const float* __restrict__ bias, const int* __restrict__ mask,
               float* __restrict__ C0, float* __restrict__ C1,
               int N, int K, int mode,
               long long strideA, long long strideB, long long strideC,
               int maskStride, float scale)
{
    extern __shared__ __align__(1024) char smem[];
    const int tid = threadIdx.x;
    const int bz = blockIdx.z;
    Ah += (size_t)bz * strideA;  Al += (size_t)bz * strideA;
    Bh += (size_t)bz * strideB;  Bl += (size_t)bz * strideB;
    C0 += (size_t)bz * strideC;
    if (C1) C1 += (size_t)bz * strideC;
    if (mask) mask += (size_t)bz * maskStride;

    const int bm = blockIdx.y * 128;
    const int bn = blockIdx.x * 256;
    const float NEG_INF = __int_as_float(0xff800000u);

#if HAS_TCGEN05
    const uint32_t sb = smem_to_u32_gen(smem);
    const uint32_t m_full0 = sb + 0,  m_full1 = sb + 8;
    const uint32_t m_emp0  = sb + 16, m_emp1  = sb + 24;
    const uint32_t m_done  = sb + 32;
    int*   s_mask = (int*)(smem + CTRL_MASK);
    float* s_bias = (float*)(smem + CTRL_BIAS);
    const int wid = tid >> 5;

    if (wid == 0) {
        TCGEN05_ALLOC(sb + 40, 256);
        TCGEN05_RELINQUISH();
    }
    if (tid == 0) {
        MBARRIER_INIT(m_full0, 256);
        MBARRIER_INIT(m_full1, 256);
        MBARRIER_INIT(m_emp0, 1);
        MBARRIER_INIT(m_emp1, 1);
        MBARRIER_INIT(m_done, 1);
    }
    if (mode == 2) s_mask[tid] = mask[bn + tid];
    else           s_bias[tid] = bias[bn + tid];
    __syncthreads();
    const uint32_t tmem = *(volatile uint32_t*)(smem + 40);

    constexpr uint32_t IDESC =
        (1u << 4)            // dtype = F32
        | (2u << 7)          // atype = TF32
        | (2u << 10)         // btype = TF32
        | ((256 / 8) << 17)  // N
        | ((128 / 16) << 24);// M

    uint64_t dAh[2], dAl[2], dBh[2], dBl[2];
#pragma unroll
    for (int s = 0; s < 2; s++) {
        uint32_t base = sb + TILES_OFF + s * STAGE_BYTES;
        dAh[s] = MAKE_SMEM_DESC(base);
        dAl[s] = MAKE_SMEM_DESC(base + 16384);
        dBh[s] = MAKE_SMEM_DESC(base + 32768);
        dBl[s] = MAKE_SMEM_DESC(base + 65536);
    }

    const int nch = K / 32;
    for (int c = 0; c < nch; c++) {
        const int s = c & 1;
        const int i = c >> 1;
        const int k0 = c * 32;
        const uint32_t m_full = s ? m_full1 : m_full0;
        const uint32_t m_emp  = s ? m_emp1  : m_emp0;
        const uint32_t st = sb + TILES_OFF + s * STAGE_BYTES;

        // producers: wait stage free, then cp.async pure copies
        MBARRIER_WAIT_PARITY(m_emp, 1 ^ (i & 1));
#pragma unroll
        for (int t = 0; t < 4; t++) {
            int idx = tid + t * 256;
            int row = idx >> 3, c4 = idx & 7;
            uint32_t sw = SMEM_SWIZZLE_128B((uint32_t)(row * 128 + c4 * 16));
            const float* pa = Ah + (size_t)(bm + row) * K + k0 + c4 * 4;
            const float* pl = Al + (size_t)(bm + row) * K + k0 + c4 * 4;
            cp_async16(st + sw, pa);
            cp_async16(st + 16384 + sw, pl);
        }
#pragma unroll
        for (int t = 0; t < 8; t++) {
            int idx = tid + t * 256;
            int row = idx >> 3, c4 = idx & 7;
            uint32_t sw = SMEM_SWIZZLE_128B((uint32_t)(row * 128 + c4 * 16));
            const float* pb = Bh + (size_t)(bn + row) * K + k0 + c4 * 4;
            const float* pl = Bl + (size_t)(bn + row) * K + k0 + c4 * 4;
            cp_async16(st + 32768 + sw, pb);
            cp_async16(st + 65536 + sw, pl);
        }
        CPASYNC_MBAR_ARRIVE_NOINC(m_full);

        // consumer: elected thread of warp 0 issues the MMAs
        if (wid == 0 && elect_one_pred()) {
            MBARRIER_WAIT_PARITY(m_full, i & 1);
            FENCE_PROXY_ASYNC_SHARED_CTA();
#pragma unroll
            for (int k = 0; k < 4; k++)
                TCGEN05_MMA_TF32_SS(tmem, dAh[s] + k * 2, dBh[s] + k * 2, IDESC,
                                    (c > 0) || (k > 0));
#pragma unroll
            for (int k = 0; k < 4; k++)
                TCGEN05_MMA_TF32_SS(tmem, dAh[s] + k * 2, dBl[s] + k * 2, IDESC, true);
#pragma unroll
            for (int k = 0; k < 4; k++)
                TCGEN05_MMA_TF32_SS(tmem, dAl[s] + k * 2, dBh[s] + k * 2, IDESC, true);
            TCGEN05_COMMIT(m_emp);
        }
    }

    if (wid == 0 && elect_one_pred()) TCGEN05_COMMIT(m_done);
    MBARRIER_WAIT_PARITY(m_done, 0);
    TCGEN05_FENCE_AFTER();

    // Epilogue: warps 0-3 read D (128 lanes x 256 cols), 32 cols per group
    if (wid < 4) {
        const int lane = tid & 31;
        const int m = bm + wid * 32 + lane;
        float* c0row = C0 + (size_t)m * N + bn;
        float* c1row = C1 ? (C1 + (size_t)m * N + bn) : nullptr;
#pragma unroll
        for (int g = 0; g < 8; g++) {
            uint32_t r[32];
            TCGEN05_LD_32X32B_X32(r, tmem + g * 32);
            TCGEN05_WAIT_LD();
            const int col0 = g * 32;
            if (mode == 2) {
#pragma unroll
                for (int j = 0; j < 32; j++) {
                    float v = __uint_as_float(r[j]) * scale;
                    if (s_mask[col0 + j] == 0) v = NEG_INF;
                    r[j] = __float_as_uint(v);
                }
#pragma unroll
                for (int j = 0; j < 8; j++)
                    *(float4*)&c0row[col0 + j * 4] = *(float4*)&r[j * 4];
            } else if (mode == 1) {
#pragma unroll
                for (int j = 0; j < 32; j++)
                    r[j] = __float_as_uint(__uint_as_float(r[j]) + s_bias[col0 + j]);
#pragma unroll
                for (int j = 0; j < 8; j++)
                    *(float4*)&c0row[col0 + j * 4] = *(float4*)&r[j * 4];
            } else {
                uint32_t rl[32];
#pragma unroll
                for (int j = 0; j < 32; j++) {
                    float v = __uint_as_float(r[j]) + s_bias[col0 + j];
                    float h = to_tf32(v);
                    r[j]  = __float_as_uint(h);
                    rl[j] = __float_as_uint(to_tf32(v - h));
                }
#pragma unroll
                for (int j = 0; j < 8; j++) {
                    *(float4*)&c0row[col0 + j * 4] = *(float4*)&r[j * 4];
                    *(float4*)&c1row[col0 + j * 4] = *(float4*)&rl[j * 4];
                }
            }
        }
    }
    __syncthreads();
    if (wid == 0) TCGEN05_DEALLOC(tmem, 256);

#else
    // ---------------- SIMT fp32 fallback (correct, not perf-tuned) ----------
    constexpr int BK = 16, TM = 8, TN = 8;
    float* As = (float*)smem;             // [BK][128]
    float* Bs = As + BK * 128;            // [BK][128]
    const int tx = tid & 15;
    const int ty = tid >> 4;

    for (int nh = 0; nh < 2; nh++) {
        const int bn2 = bn + nh * 128;
        float acc[TM][TN];
#pragma unroll
        for (int i = 0; i < TM; i++)
#pragma unroll
            for (int j = 0; j < TN; j++) acc[i][j] = 0.0f;

        for (int k0 = 0; k0 < K; k0 += BK) {
            __syncthreads();
#pragma unroll
            for (int i = 0; i < 2; i++) {
                int li  = tid + i * 256;
                int row = li >> 2;
                int kc  = (li & 3) << 2;
                float4 vh = *(const float4*)(Ah + (size_t)(bm + row) * K + k0 + kc);
                float4 vl = *(const float4*)(Al + (size_t)(bm + row) * K + k0 + kc);
                As[(kc + 0) * 128 + row] = vh.x + vl.x;
                As[(kc + 1) * 128 + row] = vh.y + vl.y;
                As[(kc + 2) * 128 + row] = vh.z + vl.z;
                As[(kc + 3) * 128 + row] = vh.w + vl.w;
                float4 wh = *(const float4*)(Bh + (size_t)(bn2 + row) * K + k0 + kc);
                float4 wl = *(const float4*)(Bl + (size_t)(bn2 + row) * K + k0 + kc);
                Bs[(kc + 0) * 128 + row] = wh.x + wl.x;
                Bs[(kc + 1) * 128 + row] = wh.y + wl.y;
                Bs[(kc + 2) * 128 + row] = wh.z + wl.z;
                Bs[(kc + 3) * 128 + row] = wh.w + wl.w;
            }
            __syncthreads();
#pragma unroll
            for (int kk = 0; kk < BK; kk++) {
                float a[TM], bb[TN];
                *(float4*)&a[0]  = *(const float4*)&As[kk * 128 + ty * TM];
                *(float4*)&a[4]  = *(const float4*)&As[kk * 128 + ty * TM + 4];
                *(float4*)&bb[0] = *(const float4*)&Bs[kk * 128 + tx * TN];
                *(float4*)&bb[4] = *(const float4*)&Bs[kk * 128 + tx * TN + 4];
#pragma unroll
                for (int i = 0; i < TM; i++)
#pragma unroll
                    for (int j = 0; j < TN; j++)
                        acc[i][j] = fmaf(a[i], bb[j], acc[i][j]);
            }
        }

        const int row0 = bm + ty * TM;
        const int col0 = bn2 + tx * TN;
#pragma unroll
        for (int i = 0; i < TM; i++) {
#pragma unroll
            for (int j = 0; j < TN; j++) {
                float v = acc[i][j];
                size_t off = (size_t)(row0 + i) * N + col0 + j;
                if (mode == 2) {
                    v *= scale;
                    if (mask[col0 + j] == 0) v = NEG_INF;
                    C0[off] = v;
                } else if (mode == 1) {
                    C0[off] = v + bias[col0 + j];
                } else {
                    v += bias[col0 + j];
                    float h = to_tf32(v);
                    C0[off] = h;
                    C1[off] = to_tf32(v - h);
                }
            }
        }
        __syncthreads();
    }
#endif
}

// ---------------------------------------------------------------------------
// Block reductions
// ---------------------------------------------------------------------------
__device__ __forceinline__ float block_reduce_max(float v)
{
    __shared__ float sm[8];
    for (int o = 16; o; o >>= 1) v = fmaxf(v, __shfl_xor_sync(0xffffffffu, v, o));
    if ((threadIdx.x & 31) == 0) sm[threadIdx.x >> 5] = v;
    __syncthreads();
    if (threadIdx.x < 32) {
        v = sm[threadIdx.x & 7];
        for (int o = 4; o; o >>= 1) v = fmaxf(v, __shfl_xor_sync(0xffffffffu, v, o));
        if (threadIdx.x == 0) sm[0] = v;
    }
    __syncthreads();
    float r = sm[0];
    __syncthreads();
    return r;
}

__device__ __forceinline__ float block_reduce_sum(float v)
{
    __shared__ float sm[8];
    for (int o = 16; o; o >>= 1) v += __shfl_xor_sync(0xffffffffu, v, o);
    if ((threadIdx.x & 31) == 0) sm[threadIdx.x >> 5] = v;
    __syncthreads();
    if (threadIdx.x < 32) {
        v = sm[threadIdx.x & 7];
        for (int o = 4; o; o >>= 1) v += __shfl_xor_sync(0xffffffffu, v, o);
        if (threadIdx.x == 0) sm[0] = v;
    }
    __syncthreads();
    float r = sm[0];
    __syncthreads();
    return r;
}

// ---------------------------------------------------------------------------
// Fused softmax + column-sum (no prob materialization)
// ---------------------------------------------------------------------------
__global__ __launch_bounds__(256)
void softmax_colsum_kernel(const float* __restrict__ P, float* __restrict__ wpart)
{
    const int ch = blockIdx.x;
    const int b  = blockIdx.y;
    const int tid = threadIdx.x;
    const float* base = P + ((size_t)b * kS + (size_t)ch * 32) * kS;

    float wacc[8];
#pragma unroll
    for (int i = 0; i < 8; i++) wacc[i] = 0.0f;

    for (int r = 0; r < 32; r++) {
        const float* p = base + (size_t)r * kS + tid * 8;
        float x[8];
        *(float4*)&x[0] = *(const float4*)&p[0];
        *(float4*)&x[4] = *(const float4*)&p[4];

        float m = x[0];
#pragma unroll
        for (int i = 1; i < 8; i++) m = fmaxf(m, x[i]);
        m = block_reduce_max(m);

        float e[8], s = 0.0f;
#pragma unroll
        for (int i = 0; i < 8; i++) {
            e[i] = __expf(x[i] - m);
            s += e[i];
        }
        s = block_reduce_sum(s);
        const float inv = 1.0f / s;
#pragma unroll
        for (int i = 0; i < 8; i++) wacc[i] = fmaf(e[i], inv, wacc[i]);
    }

    float* o = wpart + (size_t)ch * (kB * kS) + (size_t)b * kS + tid * 8;
    *(float4*)&o[0] = make_float4(wacc[0], wacc[1], wacc[2], wacc[3]);
    *(float4*)&o[4] = make_float4(wacc[4], wacc[5], wacc[6], wacc[7]);
}

__global__ __launch_bounds__(256)
void colsum_reduce_kernel(const float* __restrict__ wpart, float* __restrict__ w)
{
    const int i = blockIdx.x * 256 + threadIdx.x;
    float s = 0.0f;
#pragma unroll
    for (int c = 0; c < QCH; c++) s += wpart[(size_t)c * (kB * kS) + i];
    w[i] = s;
}

__global__ __launch_bounds__(256)
void out_part_kernel(const float* __restrict__ w, const float* __restrict__ V,
                     float* __restrict__ opart)
{
    const int chunk = blockIdx.x;
    const int b     = blockIdx.y;
    const int d     = threadIdx.x;
    const float* vb = V + ((size_t)b * kS + (size_t)chunk * 64) * kD;
    const float* wb = w + b * kS + chunk * 64;
    float s = 0.0f;
#pragma unroll
    for (int k = 0; k < 64; k++) s = fmaf(wb[k], vb[(size_t)k * kD + d], s);
    opart[(size_t)(chunk * kB + b) * kD + d] = s;
}

__global__ __launch_bounds__(256)
void out_reduce_kernel(const float* __restrict__ opart, float* __restrict__ out)
{
    const int i = blockIdx.x * 256 + threadIdx.x;
    float s = 0.0f;
#pragma unroll
    for (int c = 0; c < N_KCHUNK; c++) s += opart[(size_t)c * (kB * kD) + i];
    out[i] = s * (1.0f / (float)kS);
}

// ---------------------------------------------------------------------------
// Launch
// ---------------------------------------------------------------------------
extern "C" void kernel_launch(void* const* d_in, const int* in_sizes, int n_in,
                              void* d_out, int out_size)
{
    const float* nodes = (const float*)d_in[0];
    const int*   mask  = (const int*)  d_in[1];
    const float* Wq    = (const float*)d_in[2];
    const float* bq    = (const float*)d_in[3];
    const float* Wk    = (const float*)d_in[4];
    const float* bk    = (const float*)d_in[5];
    const float* Wv    = (const float*)d_in[6];
    const float* bv    = (const float*)d_in[7];
    float* out = (float*)d_out;

    float *Nh, *Nl, *Wqh, *Wql, *Wkh, *Wkl, *Wvh, *Wvl;
    float *Qh, *Ql, *Kh, *Kl, *V, *P, *w, *wpart, *opart;
    cudaGetSymbolAddress((void**)&Nh,  g_Nh);
    cudaGetSymbolAddress((void**)&Nl,  g_Nl);
    cudaGetSymbolAddress((void**)&Wqh, g_Wqh);
    cudaGetSymbolAddress((void**)&Wql, g_Wql);
    cudaGetSymbolAddress((void**)&Wkh, g_Wkh);
    cudaGetSymbolAddress((void**)&Wkl, g_Wkl);
    cudaGetSymbolAddress((void**)&Wvh, g_Wvh);
    cudaGetSymbolAddress((void**)&Wvl, g_Wvl);
    cudaGetSymbolAddress((void**)&Qh,  g_Qh);
    cudaGetSymbolAddress((void**)&Ql,  g_Ql);
    cudaGetSymbolAddress((void**)&Kh,  g_Kh);
    cudaGetSymbolAddress((void**)&Kl,  g_Kl);
    cudaGetSymbolAddress((void**)&V,   g_V);
    cudaGetSymbolAddress((void**)&P,   g_P);
    cudaGetSymbolAddress((void**)&w,   g_w);
    cudaGetSymbolAddress((void**)&wpart, g_wpart);
    cudaGetSymbolAddress((void**)&opart, g_opart);

    cudaFuncSetAttribute(pipe_gemm,
                         cudaFuncAttributeMaxDynamicSharedMemorySize, SMEM_TOTAL);

    dim3 blk(256);

    // 1. Split nodes and weights into tf32 hi/lo
    split_kernel<<<kM * kD / 256, blk>>>(nodes, Nh, Nl);
    split_kernel<<<kD * kD / 256, blk>>>(Wq, Wqh, Wql);
    split_kernel<<<kD * kD / 256, blk>>>(Wk, Wkh, Wkl);
    split_kernel<<<kD * kD / 256, blk>>>(Wv, Wvh, Wvl);

    // 2. Projections (BM=128, BN=256): Q,K written pre-split; V plain
    dim3 gproj(1, kM / 128, 1);
    pipe_gemm<<<gproj, blk, SMEM_TOTAL>>>(Nh, Nl, Wqh, Wql, bq, nullptr,
                                          Qh, Ql, kD, kD, 0, 0, 0, 0, 0, 1.0f);
    pipe_gemm<<<gproj, blk, SMEM_TOTAL>>>(Nh, Nl, Wkh, Wkl, bk, nullptr,
                                          Kh, Kl, kD, kD, 0, 0, 0, 0, 0, 1.0f);
    pipe_gemm<<<gproj, blk, SMEM_TOTAL>>>(Nh, Nl, Wvh, Wvl, bv, nullptr,
                                          V, nullptr, kD, kD, 1, 0, 0, 0, 0, 1.0f);

    // 3. Scores: P[b] = Q[b] @ K[b]^T / 16, masked keys -> -inf
    dim3 gsc(kS / 256, kS / 128, kB);
    pipe_gemm<<<gsc, blk, SMEM_TOTAL>>>(Qh, Ql, Kh, Kl, nullptr, mask,
                                        P, nullptr, kS, kD, 2,
                                        (long long)kS * kD,
                                        (long long)kS * kD,
                                        (long long)kS * kS, kS, 0.0625f);

    // 4. Fused softmax + column-sum, then finish
    softmax_colsum_kernel<<<dim3(QCH, kB), blk>>>(P, wpart);
    colsum_reduce_kernel<<<(kB * kS) / 256, blk>>>(wpart, w);
    out_part_kernel<<<dim3(N_KCHUNK, kB), blk>>>(w, V, opart);
    out_reduce_kernel<<<(kB * kD) / 256, blk>>>(opart, out);
}

// round 5
// speedup vs baseline: 1.2216x; 1.2216x over previous
#include <cuda_runtime.h>
#include <cstdint>
#include <math.h>

// ---------------------------------------------------------------------------
// Problem constants
// ---------------------------------------------------------------------------
static constexpr int kB = 8;
static constexpr int kS = 2048;
static constexpr int kD = 256;
static constexpr int kM = kB * kS;
static constexpr int QCH = 64;       // softmax/colsum: 32 rows per chunk
static constexpr int N_KCHUNK = 32;  // output split over keys

// Scratch (static device memory)
__device__ float g_Q[kB * kS * kD];   // tf32-rounded fp32
__device__ float g_K[kB * kS * kD];   // tf32-rounded fp32
__device__ float g_V[kB * kS * kD];   // full fp32
__device__ float g_P[(size_t)kB * kS * kS];
__device__ float g_w[kB * kS];
__device__ float g_wpart[QCH * kB * kS];
__device__ float g_opart[N_KCHUNK * kB * kD];

#if defined(__CUDA_ARCH__) && defined(__CUDA_ARCH_FEAT_SM103_ALL)
#define HAS_TCGEN05 1
#else
#define HAS_TCGEN05 0
#endif

#define SMEM_SWIZZLE_128B(byte_offset) \
    ((byte_offset) ^ (((byte_offset) >> 3) & 0x70))

__device__ __forceinline__ uint32_t smem_to_u32_gen(const void* p) {
    uint32_t a;
    asm("{ .reg .u64 t; cvta.to.shared.u64 t, %1; cvt.u32.u64 %0, t; }"
        : "=r"(a) : "l"(p));
    return a;
}

__device__ __forceinline__ float to_tf32(float x) {
    float y;
    asm("cvt.rna.tf32.f32 %0, %1;" : "=f"(y) : "f"(x));
    return y;
}

#if HAS_TCGEN05
__device__ __forceinline__ uint32_t elect_one_pred() {
    uint32_t pred;
    asm volatile(
        "{\n\t.reg .pred p;\n\t"
        "elect.sync _|p, 0xFFFFFFFF;\n\t"
        "selp.b32 %0, 1, 0, p;\n\t}"
        : "=r"(pred));
    return pred;
}

#define TCGEN05_ALLOC(smem_result_addr, nCols) \
    asm volatile("tcgen05.alloc.cta_group::1.sync.aligned.shared::cta.b32 [%0], %1;" \
                 :: "r"((uint32_t)(smem_result_addr)), "r"((uint32_t)(nCols)) : "memory")
#define TCGEN05_DEALLOC(tmem_addr, nCols) \
    asm volatile("tcgen05.dealloc.cta_group::1.sync.aligned.b32 %0, %1;" \
                 :: "r"(tmem_addr), "r"((uint32_t)(nCols)))
#define TCGEN05_RELINQUISH() \
    asm volatile("tcgen05.relinquish_alloc_permit.cta_group::1.sync.aligned;")
#define TCGEN05_COMMIT(mbar_smem_addr) \
    asm volatile("tcgen05.commit.cta_group::1.mbarrier::arrive::one.shared::cluster.b64 [%0];" \
                 :: "r"((uint32_t)(mbar_smem_addr)) : "memory")
#define TCGEN05_FENCE_AFTER() \
    asm volatile("tcgen05.fence::after_thread_sync;" ::: "memory")
#define TCGEN05_WAIT_LD() \
    asm volatile("tcgen05.wait::ld.sync.aligned;" ::: "memory")
#define MBARRIER_INIT(mbar_smem_addr, count) \
    asm volatile("mbarrier.init.shared.b64 [%0], %1;" \
                 :: "r"((uint32_t)(mbar_smem_addr)), "r"((uint32_t)(count)) : "memory")
#define FENCE_PROXY_ASYNC_SHARED_CTA() \
    asm volatile("fence.proxy.async.shared::cta;" ::: "memory")

#define MBARRIER_WAIT_PARITY(mbar_smem_addr, phase_parity) do { \
    uint32_t _mbar = (uint32_t)(mbar_smem_addr); \
    uint32_t _parity = (uint32_t)(phase_parity); \
    uint32_t _done; \
    asm volatile( \
        "{\n\t.reg .pred p;\n\t" \
        "mbarrier.try_wait.parity.acquire.cta.shared::cta.b64 p, [%1], %2;\n\t" \
        "selp.b32 %0, 1, 0, p;\n\t}" \
        : "=r"(_done) : "r"(_mbar), "r"(_parity) : "memory"); \
    if (!_done) { \
        asm volatile( \
            "{\n\t.reg .pred P1;\n\t" \
            "WAIT_LOOP_%=:\n\t" \
            "mbarrier.try_wait.parity.acquire.cta.shared::cta.b64 P1, [%0], %1, 0x989680;\n\t" \
            "@P1 bra.uni WAIT_DONE_%=;\n\t" \
            "bra.uni WAIT_LOOP_%=;\n\t" \
            "WAIT_DONE_%=:\n\t}" \
            :: "r"(_mbar), "r"(_parity) : "memory"); \
    } \
} while(0)

#define TCGEN05_LD_32X32B_X32(r, tmem_addr) \
    asm volatile( \
        "tcgen05.ld.sync.aligned.32x32b.x32.b32 " \
        "{%0, %1, %2, %3, %4, %5, %6, %7, " \
        " %8, %9, %10, %11, %12, %13, %14, %15, " \
        " %16, %17, %18, %19, %20, %21, %22, %23, " \
        " %24, %25, %26, %27, %28, %29, %30, %31}, [%32];" \
        : "=r"((r)[0]),  "=r"((r)[1]),  "=r"((r)[2]),  "=r"((r)[3]), \
          "=r"((r)[4]),  "=r"((r)[5]),  "=r"((r)[6]),  "=r"((r)[7]), \
          "=r"((r)[8]),  "=r"((r)[9]),  "=r"((r)[10]), "=r"((r)[11]), \
          "=r"((r)[12]), "=r"((r)[13]), "=r"((r)[14]), "=r"((r)[15]), \
          "=r"((r)[16]), "=r"((r)[17]), "=r"((r)[18]), "=r"((r)[19]), \
          "=r"((r)[20]), "=r"((r)[21]), "=r"((r)[22]), "=r"((r)[23]), \
          "=r"((r)[24]), "=r"((r)[25]), "=r"((r)[26]), "=r"((r)[27]), \
          "=r"((r)[28]), "=r"((r)[29]), "=r"((r)[30]), "=r"((r)[31]) \
        : "r"(tmem_addr))

#define TCGEN05_MMA_TF32_SS(d_tmem, a_desc, b_desc, idesc, enable_d) do { \
    uint32_t _en = (enable_d) ? 1u : 0u; \
    uint32_t _zero = 0u; \
    asm volatile( \
        "{\n\t.reg .pred p;\n\t" \
        "setp.ne.u32 p, %5, 0;\n\t" \
        "tcgen05.mma.cta_group::1.kind::tf32 [%0], %1, %2, %3, {%4, %4, %4, %4}, p;\n\t" \
        "}" \
        :: "r"(d_tmem), "l"(a_desc), "l"(b_desc), "r"(idesc), "r"(_zero), "r"(_en) \
        : "memory"); \
} while(0)

static constexpr uint64_t SMEM_DESC_BASE_SW128 =
    (uint64_t(2)  << 61) | (uint64_t(1) << 46) | (uint64_t(64) << 32) | (uint64_t(1) << 16);
#define MAKE_SMEM_DESC(base_addr) \
    (SMEM_DESC_BASE_SW128 | ((uint64_t)((base_addr) >> 4) & 0x3FFF))

__device__ __forceinline__ void cp_async16(uint32_t dst, const void* src) {
    asm volatile("cp.async.cg.shared.global [%0], [%1], 16;" :: "r"(dst), "l"(src));
}
#define CPASYNC_MBAR_ARRIVE_NOINC(mbar) \
    asm volatile("cp.async.mbarrier.arrive.noinc.shared::cta.b64 [%0];" \
                 :: "r"((uint32_t)(mbar)) : "memory")

// IDESC for tf32, F32 accum, M=128, N=256
static constexpr uint32_t IDESC_128x256 =
    (1u << 4) | (2u << 7) | (2u << 10) | ((256 / 8) << 17) | ((128 / 16) << 24);
#endif  // HAS_TCGEN05

// ---------------------------------------------------------------------------
// Projection GEMM (3xTF32, sync staging): C[m,n] = sum_k A[m,k]*B[n,k] + bias
// BM=128, BN=256, K=256 in 8 chunks of 32.
// mode 0: output rounded to tf32 (Q, K)    mode 1: plain fp32 (V)
// smem: [0,8) mbar, [8,12) tmem, [64,1088) bias,
//       [4096..) Ah 16K | Al 16K | Bh 32K | Bl 32K   (total 102400)
// ---------------------------------------------------------------------------
static constexpr int PROJ_SMEM = 4096 + 98304;

__global__ __launch_bounds__(256)
void proj_gemm(const float* __restrict__ A, const float* __restrict__ Bm,
               const float* __restrict__ bias, float* __restrict__ C, int mode)
{
    extern __shared__ __align__(1024) char smem[];
    const int tid = threadIdx.x;
    const int bm = blockIdx.y * 128;
    constexpr int N = 256, K = 256;

#if HAS_TCGEN05
    const uint32_t sb = smem_to_u32_gen(smem);
    const uint32_t mbar = sb;
    float* s_bias = (float*)(smem + 64);
    const int wid = tid >> 5;

    if (wid == 0) { TCGEN05_ALLOC(sb + 8, 256); TCGEN05_RELINQUISH(); }
    if (tid == 0) MBARRIER_INIT(mbar, 1);
    s_bias[tid] = bias[tid];
    __syncthreads();
    const uint32_t tmem = *(volatile uint32_t*)(smem + 8);

    const uint32_t tAh = sb + 4096;
    const uint32_t tAl = tAh + 16384;
    const uint32_t tBh = tAl + 16384;
    const uint32_t tBl = tBh + 32768;
    const uint64_t dAh = MAKE_SMEM_DESC(tAh);
    const uint64_t dAl = MAKE_SMEM_DESC(tAl);
    const uint64_t dBh = MAKE_SMEM_DESC(tBh);
    const uint64_t dBl = MAKE_SMEM_DESC(tBl);

    for (int c = 0; c < K / 32; c++) {
        const int k0 = c * 32;
        __syncthreads();
        // A tile 128x32: 1024 float4 -> 4 per thread, split in-register
#pragma unroll
        for (int t = 0; t < 4; t++) {
            int idx = tid + t * 256;
            int row = idx >> 3, c4 = idx & 7;
            uint32_t sw = SMEM_SWIZZLE_128B((uint32_t)(row * 128 + c4 * 16));
            float4 v = *(const float4*)(A + (size_t)(bm + row) * K + k0 + c4 * 4);
            float4 h, l;
            h.x = to_tf32(v.x); l.x = to_tf32(v.x - h.x);
            h.y = to_tf32(v.y); l.y = to_tf32(v.y - h.y);
            h.z = to_tf32(v.z); l.z = to_tf32(v.z - h.z);
            h.w = to_tf32(v.w); l.w = to_tf32(v.w - h.w);
            *(float4*)(smem + (tAh - sb) + sw) = h;
            *(float4*)(smem + (tAl - sb) + sw) = l;
        }
        // B tile 256x32: 2048 float4 -> 8 per thread
#pragma unroll
        for (int t = 0; t < 8; t++) {
            int idx = tid + t * 256;
            int row = idx >> 3, c4 = idx & 7;
            uint32_t sw = SMEM_SWIZZLE_128B((uint32_t)(row * 128 + c4 * 16));
            float4 v = *(const float4*)(Bm + (size_t)row * K + k0 + c4 * 4);
            float4 h, l;
            h.x = to_tf32(v.x); l.x = to_tf32(v.x - h.x);
            h.y = to_tf32(v.y); l.y = to_tf32(v.y - h.y);
            h.z = to_tf32(v.z); l.z = to_tf32(v.z - h.z);
            h.w = to_tf32(v.w); l.w = to_tf32(v.w - h.w);
            *(float4*)(smem + (tBh - sb) + sw) = h;
            *(float4*)(smem + (tBl - sb) + sw) = l;
        }
        FENCE_PROXY_ASYNC_SHARED_CTA();
        __syncthreads();

        if (wid == 0 && elect_one_pred()) {
#pragma unroll
            for (int k = 0; k < 4; k++)
                TCGEN05_MMA_TF32_SS(tmem, dAh + k * 2, dBh + k * 2, IDESC_128x256,
                                    (c > 0) || (k > 0));
#pragma unroll
            for (int k = 0; k < 4; k++)
                TCGEN05_MMA_TF32_SS(tmem, dAh + k * 2, dBl + k * 2, IDESC_128x256, true);
#pragma unroll
            for (int k = 0; k < 4; k++)
                TCGEN05_MMA_TF32_SS(tmem, dAl + k * 2, dBh + k * 2, IDESC_128x256, true);
            TCGEN05_COMMIT(mbar);
        }
        MBARRIER_WAIT_PARITY(mbar, c & 1);
    }

    TCGEN05_FENCE_AFTER();

    if (wid < 4) {
        const int m = bm + wid * 32 + (tid & 31);
        float* crow = C + (size_t)m * N;
#pragma unroll
        for (int g = 0; g < 8; g++) {
            uint32_t r[32];
            TCGEN05_LD_32X32B_X32(r, tmem + g * 32);
            TCGEN05_WAIT_LD();
            const int col0 = g * 32;
#pragma unroll
            for (int j = 0; j < 32; j++) {
                float v = __uint_as_float(r[j]) + s_bias[col0 + j];
                if (mode == 0) v = to_tf32(v);
                r[j] = __float_as_uint(v);
            }
#pragma unroll
            for (int j = 0; j < 8; j++)
                *(float4*)&crow[col0 + j * 4] = *(float4*)&r[j * 4];
        }
    }
    __syncthreads();
    if (wid == 0) TCGEN05_DEALLOC(tmem, 256);

#else
    // SIMT fallback
    constexpr int BK = 16, TM = 8, TN = 8;
    float* As = (float*)smem;
    float* Bs = As + BK * 128;
    const int tx = tid & 15, ty = tid >> 4;

    for (int nh = 0; nh < 2; nh++) {
        const int bn2 = nh * 128;
        float acc[TM][TN];
#pragma unroll
        for (int i = 0; i < TM; i++)
#pragma unroll
            for (int j = 0; j < TN; j++) acc[i][j] = 0.0f;

        for (int k0 = 0; k0 < K; k0 += BK) {
            __syncthreads();
#pragma unroll
            for (int i = 0; i < 2; i++) {
                int li = tid + i * 256;
                int row = li >> 2, kc = (li & 3) << 2;
                float4 va = *(const float4*)(A + (size_t)(bm + row) * K + k0 + kc);
                As[(kc + 0) * 128 + row] = va.x; As[(kc + 1) * 128 + row] = va.y;
                As[(kc + 2) * 128 + row] = va.z; As[(kc + 3) * 128 + row] = va.w;
                float4 vb = *(const float4*)(Bm + (size_t)(bn2 + row) * K + k0 + kc);
                Bs[(kc + 0) * 128 + row] = vb.x; Bs[(kc + 1) * 128 + row] = vb.y;
                Bs[(kc + 2) * 128 + row] = vb.z; Bs[(kc + 3) * 128 + row] = vb.w;
            }
            __syncthreads();
#pragma unroll
            for (int kk = 0; kk < BK; kk++) {
                float a[TM], bb[TN];
                *(float4*)&a[0]  = *(const float4*)&As[kk * 128 + ty * TM];
                *(float4*)&a[4]  = *(const float4*)&As[kk * 128 + ty * TM + 4];
                *(float4*)&bb[0] = *(const float4*)&Bs[kk * 128 + tx * TN];
                *(float4*)&bb[4] = *(const float4*)&Bs[kk * 128 + tx * TN + 4];
#pragma unroll
                for (int i = 0; i < TM; i++)
#pragma unroll
                    for (int j = 0; j < TN; j++)
                        acc[i][j] = fmaf(a[i], bb[j], acc[i][j]);
            }
        }
        const int row0 = bm + ty * TM, col0 = bn2 + tx * TN;
#pragma unroll
        for (int i = 0; i < TM; i++)
#pragma unroll
            for (int j = 0; j < TN; j++) {
                float v = acc[i][j] + bias[col0 + j];
                if (mode == 0) v = to_tf32(v);
                C[(size_t)(row0 + i) * N + col0 + j] = v;
            }
        __syncthreads();
    }
#endif
}

// ---------------------------------------------------------------------------
// Scores GEMM (single tf32, cp.async 2-stage pipeline):
//   P[b,m,n] = (Q[b,m,:] . K[b,n,:]) * scale, masked n -> -inf
// BM=128, BN=256, K=256 in 8 chunks of 32. Q,K already tf32-rounded.
// smem: [0,8) full0 [8,16) full1 [16,24) emp0 [24,32) emp1 [32,40) done
//       [40,44) tmem, [64,1088) mask[256]
//       [4096..) stage0 {A 16K | B 32K}, stage1 {A 16K | B 32K}  total 102400
// ---------------------------------------------------------------------------
static constexpr int SC_STAGE = 49152;
static constexpr int SC_SMEM = 4096 + 2 * SC_STAGE;

__global__ __launch_bounds__(256)
void score_gemm(const float* __restrict__ Q, const float* __restrict__ Kmat,
                const int* __restrict__ mask, float* __restrict__ P, float scale)
{
    extern __shared__ __align__(1024) char smem[];
    const int tid = threadIdx.x;
    const int bz = blockIdx.z;
    const float* Aq = Q    + (size_t)bz * kS * kD;
    const float* Bk = Kmat + (size_t)bz * kS * kD;
    float* C = P + (size_t)bz * kS * kS;
    const int* mk = mask + (size_t)bz * kS;

    const int bm = blockIdx.y * 128;
    const int bn = blockIdx.x * 256;
    const float NEG_INF = __int_as_float(0xff800000u);

#if HAS_TCGEN05
    const uint32_t sb = smem_to_u32_gen(smem);
    const uint32_t m_full0 = sb + 0,  m_full1 = sb + 8;
    const uint32_t m_emp0  = sb + 16, m_emp1  = sb + 24;
    const uint32_t m_done  = sb + 32;
    int* s_mask = (int*)(smem + 64);
    const int wid = tid >> 5;

    if (wid == 0) { TCGEN05_ALLOC(sb + 40, 256); TCGEN05_RELINQUISH(); }
    if (tid == 0) {
        MBARRIER_INIT(m_full0, 256);
        MBARRIER_INIT(m_full1, 256);
        MBARRIER_INIT(m_emp0, 1);
        MBARRIER_INIT(m_emp1, 1);
        MBARRIER_INIT(m_done, 1);
    }
    s_mask[tid] = mk[bn + tid];
    __syncthreads();
    const uint32_t tmem = *(volatile uint32_t*)(smem + 40);

    uint64_t dA[2], dB[2];
#pragma unroll
    for (int s = 0; s < 2; s++) {
        uint32_t base = sb + 4096 + s * SC_STAGE;
        dA[s] = MAKE_SMEM_DESC(base);
        dB[s] = MAKE_SMEM_DESC(base + 16384);
    }

    for (int c = 0; c < 8; c++) {
        const int s = c & 1;
        const int i = c >> 1;
        const int k0 = c * 32;
        const uint32_t m_full = s ? m_full1 : m_full0;
        const uint32_t m_emp  = s ? m_emp1  : m_emp0;
        const uint32_t st = sb + 4096 + s * SC_STAGE;

        MBARRIER_WAIT_PARITY(m_emp, 1 ^ (i & 1));
#pragma unroll
        for (int t = 0; t < 4; t++) {
            int idx = tid + t * 256;
            int row = idx >> 3, c4 = idx & 7;
            uint32_t sw = SMEM_SWIZZLE_128B((uint32_t)(row * 128 + c4 * 16));
            cp_async16(st + sw, Aq + (size_t)(bm + row) * kD + k0 + c4 * 4);
        }
#pragma unroll
        for (int t = 0; t < 8; t++) {
            int idx = tid + t * 256;
            int row = idx >> 3, c4 = idx & 7;
            uint32_t sw = SMEM_SWIZZLE_128B((uint32_t)(row * 128 + c4 * 16));
            cp_async16(st + 16384 + sw, Bk + (size_t)(bn + row) * kD + k0 + c4 * 4);
        }
        CPASYNC_MBAR_ARRIVE_NOINC(m_full);

        if (wid == 0 && elect_one_pred()) {
            MBARRIER_WAIT_PARITY(m_full, i & 1);
            FENCE_PROXY_ASYNC_SHARED_CTA();
#pragma unroll
            for (int k = 0; k < 4; k++)
                TCGEN05_MMA_TF32_SS(tmem, dA[s] + k * 2, dB[s] + k * 2, IDESC_128x256,
                                    (c > 0) || (k > 0));
            TCGEN05_COMMIT(m_emp);
        }
    }

    if (wid == 0 && elect_one_pred()) TCGEN05_COMMIT(m_done);
    MBARRIER_WAIT_PARITY(m_done, 0);
    TCGEN05_FENCE_AFTER();

    if (wid < 4) {
        const int m = bm + wid * 32 + (tid & 31);
        float* crow = C + (size_t)m * kS + bn;
#pragma unroll
        for (int g = 0; g < 8; g++) {
            uint32_t r[32];
            TCGEN05_LD_32X32B_X32(r, tmem + g * 32);
            TCGEN05_WAIT_LD();
            const int col0 = g * 32;
#pragma unroll
            for (int j = 0; j < 32; j++) {
                float v = __uint_as_float(r[j]) * scale;
                if (s_mask[col0 + j] == 0) v = NEG_INF;
                r[j] = __float_as_uint(v);
            }
#pragma unroll
            for (int j = 0; j < 8; j++)
                *(float4*)&crow[col0 + j * 4] = *(float4*)&r[j * 4];
        }
    }
    __syncthreads();
    if (wid == 0) TCGEN05_DEALLOC(tmem, 256);

#else
    // SIMT fallback
    constexpr int BK = 16, TM = 8, TN = 8;
    float* As = (float*)smem;
    float* Bs = As + BK * 128;
    const int tx = tid & 15, ty = tid >> 4;

    for (int nh = 0; nh < 2; nh++) {
        const int bn2 = bn + nh * 128;
        float acc[TM][TN];
#pragma unroll
        for (int i = 0; i < TM; i++)
#pragma unroll
            for (int j = 0; j < TN; j++) acc[i][j] = 0.0f;

        for (int k0 = 0; k0 < kD; k0 += BK) {
            __syncthreads();
#pragma unroll
            for (int i = 0; i < 2; i++) {
                int li = tid + i * 256;
                int row = li >> 2, kc = (li & 3) << 2;
                float4 va = *(const float4*)(Aq + (size_t)(bm + row) * kD + k0 + kc);
                As[(kc + 0) * 128 + row] = va.x; As[(kc + 1) * 128 + row] = va.y;
                As[(kc + 2) * 128 + row] = va.z; As[(kc + 3) * 128 + row] = va.w;
                float4 vb = *(const float4*)(Bk + (size_t)(bn2 + row) * kD + k0 + kc);
                Bs[(kc + 0) * 128 + row] = vb.x; Bs[(kc + 1) * 128 + row] = vb.y;
                Bs[(kc + 2) * 128 + row] = vb.z; Bs[(kc + 3) * 128 + row] = vb.w;
            }
            __syncthreads();
#pragma unroll
            for (int kk = 0; kk < BK; kk++) {
                float a[TM], bb[TN];
                *(float4*)&a[0]  = *(const float4*)&As[kk * 128 + ty * TM];
                *(float4*)&a[4]  = *(const float4*)&As[kk * 128 + ty * TM + 4];
                *(float4*)&bb[0] = *(const float4*)&Bs[kk * 128 + tx * TN];
                *(float4*)&bb[4] = *(const float4*)&Bs[kk * 128 + tx * TN + 4];
#pragma unroll
                for (int i = 0; i < TM; i++)
#pragma unroll
                    for (int j = 0; j < TN; j++)
                        acc[i][j] = fmaf(a[i], bb[j], acc[i][j]);
            }
        }
        const int row0 = bm + ty * TM, col0 = bn2 + tx * TN;
#pragma unroll
        for (int i = 0; i < TM; i++)
#pragma unroll
            for (int j = 0; j < TN; j++) {
                float v = acc[i][j] * scale;
                if (mk[col0 + j] == 0) v = NEG_INF;
                C[(size_t)(row0 + i) * kS + col0 + j] = v;
            }
        __syncthreads();
    }
#endif
}

// ---------------------------------------------------------------------------
// Block reductions
// ---------------------------------------------------------------------------
__device__ __forceinline__ float block_reduce_max(float v)
{
    __shared__ float sm[8];
    for (int o = 16; o; o >>= 1) v = fmaxf(v, __shfl_xor_sync(0xffffffffu, v, o));
    if ((threadIdx.x & 31) == 0) sm[threadIdx.x >> 5] = v;
    __syncthreads();
    if (threadIdx.x < 32) {
        v = sm[threadIdx.x & 7];
        for (int o = 4; o; o >>= 1) v = fmaxf(v, __shfl_xor_sync(0xffffffffu, v, o));
        if (threadIdx.x == 0) sm[0] = v;
    }
    __syncthreads();
    float r = sm[0];
    __syncthreads();
    return r;
}

__device__ __forceinline__ float block_reduce_sum(float v)
{
    __shared__ float sm[8];
    for (int o = 16; o; o >>= 1) v += __shfl_xor_sync(0xffffffffu, v, o);
    if ((threadIdx.x & 31) == 0) sm[threadIdx.x >> 5] = v;
    __syncthreads();
    if (threadIdx.x < 32) {
        v = sm[threadIdx.x & 7];
        for (int o = 4; o; o >>= 1) v += __shfl_xor_sync(0xffffffffu, v, o);
        if (threadIdx.x == 0) sm[0] = v;
    }
    __syncthreads();
    float r = sm[0];
    __syncthreads();
    return r;
}

// ---------------------------------------------------------------------------
// Fused softmax + column-sum (no prob materialization)
// ---------------------------------------------------------------------------
__global__ __launch_bounds__(256)
void softmax_colsum_kernel(const float* __restrict__ P, float* __restrict__ wpart)
{
    const int ch = blockIdx.x;
    const int b  = blockIdx.y;
    const int tid = threadIdx.x;
    const float* base = P + ((size_t)b * kS + (size_t)ch * 32) * kS;

    float wacc[8];
#pragma unroll
    for (int i = 0; i < 8; i++) wacc[i] = 0.0f;

    for (int r = 0; r < 32; r++) {
        const float* p = base + (size_t)r * kS + tid * 8;
        float x[8];
        *(float4*)&x[0] = *(const float4*)&p[0];
        *(float4*)&x[4] = *(const float4*)&p[4];

        float m = x[0];
#pragma unroll
        for (int i = 1; i < 8; i++) m = fmaxf(m, x[i]);
        m = block_reduce_max(m);

        float e[8], s = 0.0f;
#pragma unroll
        for (int i = 0; i < 8; i++) {
            e[i] = __expf(x[i] - m);
            s += e[i];
        }
        s = block_reduce_sum(s);
        const float inv = 1.0f / s;
#pragma unroll
        for (int i = 0; i < 8; i++) wacc[i] = fmaf(e[i], inv, wacc[i]);
    }

    float* o = wpart + (size_t)ch * (kB * kS) + (size_t)b * kS + tid * 8;
    *(float4*)&o[0] = make_float4(wacc[0], wacc[1], wacc[2], wacc[3]);
    *(float4*)&o[4] = make_float4(wacc[4], wacc[5], wacc[6], wacc[7]);
}

__global__ __launch_bounds__(256)
void colsum_reduce_kernel(const float* __restrict__ wpart, float* __restrict__ w)
{
    const int i = blockIdx.x * 256 + threadIdx.x;
    float s = 0.0f;
#pragma unroll
    for (int c = 0; c < QCH; c++) s += wpart[(size_t)c * (kB * kS) + i];
    w[i] = s;
}

__global__ __launch_bounds__(256)
void out_part_kernel(const float* __restrict__ w, const float* __restrict__ V,
                     float* __restrict__ opart)
{
    const int chunk = blockIdx.x;
    const int b     = blockIdx.y;
    const int d     = threadIdx.x;
    const float* vb = V + ((size_t)b * kS + (size_t)chunk * 64) * kD;
    const float* wb = w + b * kS + chunk * 64;
    float s = 0.0f;
#pragma unroll
    for (int k = 0; k < 64; k++) s = fmaf(wb[k], vb[(size_t)k * kD + d], s);
    opart[(size_t)(chunk * kB + b) * kD + d] = s;
}

__global__ __launch_bounds__(256)
void out_reduce_kernel(const float* __restrict__ opart, float* __restrict__ out)
{
    const int i = blockIdx.x * 256 + threadIdx.x;
    float s = 0.0f;
#pragma unroll
    for (int c = 0; c < N_KCHUNK; c++) s += opart[(size_t)c * (kB * kD) + i];
    out[i] = s * (1.0f / (float)kS);
}

// ---------------------------------------------------------------------------
// Launch
// ---------------------------------------------------------------------------
extern "C" void kernel_launch(void* const* d_in, const int* in_sizes, int n_in,
                              void* d_out, int out_size)
{
    const float* nodes = (const float*)d_in[0];
    const int*   mask  = (const int*)  d_in[1];
    const float* Wq    = (const float*)d_in[2];
    const float* bq    = (const float*)d_in[3];
    const float* Wk    = (const float*)d_in[4];
    const float* bk    = (const float*)d_in[5];
    const float* Wv    = (const float*)d_in[6];
    const float* bv    = (const float*)d_in[7];
    float* out = (float*)d_out;

    float *Q, *K, *V, *P, *w, *wpart, *opart;
    cudaGetSymbolAddress((void**)&Q,     g_Q);
    cudaGetSymbolAddress((void**)&K,     g_K);
    cudaGetSymbolAddress((void**)&V,     g_V);
    cudaGetSymbolAddress((void**)&P,     g_P);
    cudaGetSymbolAddress((void**)&w,     g_w);
    cudaGetSymbolAddress((void**)&wpart, g_wpart);
    cudaGetSymbolAddress((void**)&opart, g_opart);

    cudaFuncSetAttribute(proj_gemm,
                         cudaFuncAttributeMaxDynamicSharedMemorySize, PROJ_SMEM);
    cudaFuncSetAttribute(score_gemm,
                         cudaFuncAttributeMaxDynamicSharedMemorySize, SC_SMEM);

    dim3 blk(256);

    // 1. Projections (3xTF32). Q,K written tf32-rounded, V full fp32.
    dim3 gproj(1, kM / 128, 1);
    proj_gemm<<<gproj, blk, PROJ_SMEM>>>(nodes, Wq, bq, Q, 0);
    proj_gemm<<<gproj, blk, PROJ_SMEM>>>(nodes, Wk, bk, K, 0);
    proj_gemm<<<gproj, blk, PROJ_SMEM>>>(nodes, Wv, bv, V, 1);

    // 2. Scores (single tf32, pipelined): P = Q K^T / 16, mask -> -inf
    dim3 gsc(kS / 256, kS / 128, kB);
    score_gemm<<<gsc, blk, SC_SMEM>>>(Q, K, mask, P, 0.0625f);

    // 3. Fused softmax + column-sum, then finish
    softmax_colsum_kernel<<<dim3(QCH, kB), blk>>>(P, wpart);
    colsum_reduce_kernel<<<(kB * kS) / 256, blk>>>(wpart, w);
    out_part_kernel<<<dim3(N_KCHUNK, kB), blk>>>(w, V, opart);
    out_reduce_kernel<<<(kB * kD) / 256, blk>>>(opart, out);
}